// round 1
// baseline (speedup 1.0000x reference)
#include <cuda_runtime.h>
#include <cuda_bf16.h>

#define BATCH 256
#define NQ 1000
#define NC 80
#define TOPK 300
#define THRESH 0.05f
#define SORT_N 1024

// Scratch (no allocations allowed in kernel_launch)
__device__ unsigned long long g_keys[BATCH * NQ];
__device__ float g_scores[BATCH * NQ];
__device__ int   g_labels[BATCH * NQ];

// Order-preserving bijection float -> uint32 (monotone increasing)
__device__ __forceinline__ unsigned int fkey(float f) {
    unsigned int u = __float_as_uint(f);
    return (u & 0x80000000u) ? ~u : (u | 0x80000000u);
}

// Kernel 1: one warp per query. Max+argmax over 80 logits (tie -> lowest class),
// sigmoid of max (monotone), build 64-bit sort key with index tie-break.
__global__ void __launch_bounds__(256) k_maxarg(const float* __restrict__ logits) {
    int warp = (blockIdx.x * blockDim.x + threadIdx.x) >> 5;
    int lane = threadIdx.x & 31;
    if (warp >= BATCH * NQ) return;

    const float4* row = reinterpret_cast<const float4*>(logits + (size_t)warp * NC);
    float v = -3.402823466e38f;
    int   c = 127;
    if (lane < NC / 4) {  // 20 lanes, one float4 each
        float4 x = row[lane];
        v = x.x; c = 4 * lane;
        if (x.y > v) { v = x.y; c = 4 * lane + 1; }
        if (x.z > v) { v = x.z; c = 4 * lane + 2; }
        if (x.w > v) { v = x.w; c = 4 * lane + 3; }
    }
    #pragma unroll
    for (int off = 16; off; off >>= 1) {
        float v2 = __shfl_xor_sync(0xffffffffu, v, off);
        int   c2 = __shfl_xor_sync(0xffffffffu, c, off);
        if (v2 > v || (v2 == v && c2 < c)) { v = v2; c = c2; }
    }
    if (lane == 0) {
        float s = 1.0f / (1.0f + expf(-v));           // sigmoid of max logit
        float masked = (s > THRESH) ? s : -1.0f;
        int qi = warp % NQ;
        g_scores[warp] = s;
        g_labels[warp] = c;
        g_keys[warp] = ((unsigned long long)fkey(masked) << 10)
                     | (unsigned long long)(1023 - qi);
    }
}

// Kernel 2: one block per batch. Bitonic sort 1024 keys descending in smem,
// then first 300 sorted entries -> gather label/box, convert+scale, write out.
__global__ void __launch_bounds__(512) k_topk(const float* __restrict__ boxes,
                                              const float* __restrict__ tsizes,
                                              float* __restrict__ out) {
    __shared__ unsigned long long sk[SORT_N];
    int b = blockIdx.x;
    int t = threadIdx.x;

    for (int i = t; i < SORT_N; i += blockDim.x)
        sk[i] = (i < NQ) ? g_keys[b * NQ + i] : 0ULL;  // pad sorts below everything real
    __syncthreads();

    // Bitonic sort, final order descending
    for (int k = 2; k <= SORT_N; k <<= 1) {
        for (int j = k >> 1; j > 0; j >>= 1) {
            #pragma unroll 1
            for (int i = t; i < SORT_N; i += 512) {
                int p = i ^ j;
                if (p > i) {
                    unsigned long long a = sk[i], bb = sk[p];
                    bool desc = ((i & k) == 0);
                    if (desc ? (a < bb) : (a > bb)) { sk[i] = bb; sk[p] = a; }
                }
            }
            __syncthreads();
        }
    }

    float img_h = tsizes[b * 2 + 0];
    float img_w = tsizes[b * 2 + 1];

    for (int j = t; j < TOPK; j += blockDim.x) {
        unsigned long long key = sk[j];
        int qi = 1023 - (int)(key & 1023ULL);
        int o = b * TOPK + j;
        float* ob = out + 2 * BATCH * TOPK + (size_t)o * 4;

        if (qi >= NQ) {  // padding key (can't happen with 1000 real entries; defensive)
            out[o] = 0.0f;
            out[BATCH * TOPK + o] = -1.0f;
            ob[0] = ob[1] = ob[2] = ob[3] = 0.0f;
            continue;
        }
        float s = g_scores[b * NQ + qi];
        bool valid = s > THRESH;
        float4 bx = reinterpret_cast<const float4*>(boxes)[b * NQ + qi];
        float x0 = (bx.x - 0.5f * bx.z) * img_w;
        float y0 = (bx.y - 0.5f * bx.w) * img_h;
        float x1 = (bx.x + 0.5f * bx.z) * img_w;
        float y1 = (bx.y + 0.5f * bx.w) * img_h;

        out[o] = valid ? s : 0.0f;
        out[BATCH * TOPK + o] = valid ? (float)g_labels[b * NQ + qi] : -1.0f;
        ob[0] = valid ? x0 : 0.0f;
        ob[1] = valid ? y0 : 0.0f;
        ob[2] = valid ? x1 : 0.0f;
        ob[3] = valid ? y1 : 0.0f;
    }
}

extern "C" void kernel_launch(void* const* d_in, const int* in_sizes, int n_in,
                              void* d_out, int out_size) {
    const float* pred_logits  = (const float*)d_in[0];
    const float* pred_boxes   = (const float*)d_in[1];
    const float* target_sizes = (const float*)d_in[2];
    float* out = (float*)d_out;

    // Kernel 1: 256000 warps, 8 warps/block
    int total_warps = BATCH * NQ;
    int blocks1 = (total_warps * 32 + 255) / 256;
    k_maxarg<<<blocks1, 256>>>(pred_logits);

    // Kernel 2: one block per batch
    k_topk<<<BATCH, 512>>>(pred_boxes, target_sizes, out);
}